// round 4
// baseline (speedup 1.0000x reference)
#include <cuda_runtime.h>
#include <stdint.h>
#include <math_constants.h>

// BoxLoss: elementwise CIoU + masked reduction, fused single kernel.
//   0: predicts_bbox [B,A,4] f32
//   1: targets_bbox  [B,A,4] f32
//   2: valid_masks   [B,A]   bool/f32/i32 (dtype sniffed per-block)
//   3: box_norm      [B,A]   f32
//   4: cls_norm      []      f32
// Output: d_out[0] = loss_iou, d_out[1..N] = masked iou.

#define NTHREADS    256
#define MAX_BLOCKS  8192

__device__ float        g_partials[MAX_BLOCKS];
__device__ unsigned int g_ticket = 0;

__device__ __forceinline__ int sniff_mask_mode(const uint32_t* mask_words) {
    uint32_t w = mask_words[threadIdx.x];          // first 1024 bytes
    int f32flag = 0, u8flag = 0;
    #pragma unroll
    for (int b = 0; b < 4; b++) {
        uint32_t byte = (w >> (8 * b)) & 0xFFu;
        if (byte == 0x3Fu || byte == 0x80u) f32flag = 1;
        if (byte == 0x01u && b != 0)        u8flag  = 1;
    }
    unsigned any_f32 = __ballot_sync(0xFFFFFFFFu, f32flag);
    unsigned any_u8  = __ballot_sync(0xFFFFFFFFu, u8flag);

    __shared__ int s_f32, s_u8, s_mode;
    if (threadIdx.x == 0) { s_f32 = 0; s_u8 = 0; }
    __syncthreads();
    if ((threadIdx.x & 31) == 0) {
        if (any_f32) atomicOr(&s_f32, 1);
        if (any_u8)  atomicOr(&s_u8, 1);
    }
    __syncthreads();
    if (threadIdx.x == 0) s_mode = s_f32 ? 0 : (s_u8 ? 1 : 2);
    __syncthreads();
    return s_mode;
}

__device__ __forceinline__ float block_reduce_sum(float v) {
    __shared__ float s_warp[NTHREADS / 32];
    #pragma unroll
    for (int off = 16; off > 0; off >>= 1)
        v += __shfl_down_sync(0xFFFFFFFFu, v, off);
    int lane = threadIdx.x & 31;
    int wid  = threadIdx.x >> 5;
    if (lane == 0) s_warp[wid] = v;
    __syncthreads();
    float r = 0.0f;
    if (threadIdx.x == 0) {
        #pragma unroll
        for (int w = 0; w < NTHREADS / 32; w++) r += s_warp[w];
    }
    return r;  // valid in thread 0 only
}

// branchless minimax atan, full range, max err ~1e-6
__device__ __forceinline__ float fast_atan(float t) {
    float at  = fabsf(t);
    bool  inv = at > 1.0f;
    float z   = inv ? __fdividef(1.0f, at) : at;   // z in [0,1]
    float z2  = z * z;
    float p   =              -0.0117212f;
    p = fmaf(p, z2,  0.05265332f);
    p = fmaf(p, z2, -0.11643287f);
    p = fmaf(p, z2,  0.19354346f);
    p = fmaf(p, z2, -0.33262347f);
    p = fmaf(p, z2,  0.99997726f);
    p *= z;
    float r = inv ? (CUDART_PIO2_F - p) : p;
    return copysignf(r, t);
}

// one element of masked CIoU; returns masked iou, accumulates loss term
__device__ __forceinline__ float ciou_elem(float4 a, float4 b, float m,
                                           float bn, float& acc) {
    const float EPS   = 1e-9f;
    const float C4PI2 = 4.0f / (CUDART_PI_F * CUDART_PI_F);

    float iw = fmaxf(fminf(a.z, b.z) - fmaxf(a.x, b.x), 0.0f);
    float ih = fmaxf(fminf(a.w, b.w) - fmaxf(a.y, b.y), 0.0f);
    float inter  = iw * ih;
    float wa = a.z - a.x, ha = a.w - a.y;
    float wb = b.z - b.x, hb = b.w - b.y;
    float uni = wa * ha + wb * hb - inter;
    float iou = __fdividef(inter, uni + EPS);

    float cw = fmaxf(a.z, b.z) - fminf(a.x, b.x);
    float ch = fmaxf(a.w, b.w) - fminf(a.y, b.y);
    float c2 = cw * cw + ch * ch + EPS;

    float dx   = (b.x + b.z - a.x - a.z) * 0.5f;
    float dy   = (b.y + b.w - a.y - a.w) * 0.5f;
    float rho2 = dx * dx + dy * dy;

    // atan(x) - atan(y) == atan((x-y)/(1+xy))  for x,y >= 0 (no wrap)
    float x = __fdividef(wb, hb + EPS);
    float y = __fdividef(wa, ha + EPS);
    float t = __fdividef(x - y, fmaf(x, y, 1.0f));
    float d = fast_atan(t);
    float v = C4PI2 * d * d;
    float alpha = __fdividef(v, 1.0f - iou + v + EPS);

    float ciou_m = (iou - __fdividef(rho2, c2) - alpha * v) * m;
    acc += (1.0f - ciou_m) * bn * m;
    return ciou_m;
}

template <int MODE>
__device__ __forceinline__ void load_mask4(const void* mask, int q,
                                           float& m0, float& m1,
                                           float& m2, float& m3) {
    if (MODE == 0) {
        float4 mm = ((const float4*)mask)[q];
        m0 = mm.x; m1 = mm.y; m2 = mm.z; m3 = mm.w;
    } else if (MODE == 1) {
        uchar4 mm = ((const uchar4*)mask)[q];
        m0 = mm.x ? 1.0f : 0.0f; m1 = mm.y ? 1.0f : 0.0f;
        m2 = mm.z ? 1.0f : 0.0f; m3 = mm.w ? 1.0f : 0.0f;
    } else {
        int4 mm = ((const int4*)mask)[q];
        m0 = mm.x ? 1.0f : 0.0f; m1 = mm.y ? 1.0f : 0.0f;
        m2 = mm.z ? 1.0f : 0.0f; m3 = mm.w ? 1.0f : 0.0f;
    }
}

template <int MODE>
__device__ __forceinline__ float quad_work(const float4* __restrict__ pb,
                                           const float4* __restrict__ tb,
                                           const void*   __restrict__ mask,
                                           const float*  __restrict__ box_norm,
                                           float*        __restrict__ iou_out,
                                           int n) {
    float acc = 0.0f;
    int q     = blockIdx.x * blockDim.x + threadIdx.x;   // quad index
    int nquad = n >> 2;

    if (q < nquad) {
        int i = q * 4;
        // batch all loads up front: 8 x LDG.128 boxes + mask + box_norm
        float4 a0 = pb[i], a1 = pb[i+1], a2 = pb[i+2], a3 = pb[i+3];
        float4 b0 = tb[i], b1 = tb[i+1], b2 = tb[i+2], b3 = tb[i+3];
        float4 bn = ((const float4*)box_norm)[q];
        float  m0, m1, m2, m3;
        load_mask4<MODE>(mask, q, m0, m1, m2, m3);

        float r0 = ciou_elem(a0, b0, m0, bn.x, acc);
        float r1 = ciou_elem(a1, b1, m1, bn.y, acc);
        float r2 = ciou_elem(a2, b2, m2, bn.z, acc);
        float r3 = ciou_elem(a3, b3, m3, bn.w, acc);
        // vector store
        ((float4*)0)[0];  // (no-op placeholder removed by compiler? avoid UB)
        float4 r = make_float4(r0, r1, r2, r3);
        // iou_out = out+1 is only 4-byte aligned -> scalar stores
        iou_out[i]   = r.x;
        iou_out[i+1] = r.y;
        iou_out[i+2] = r.z;
        iou_out[i+3] = r.w;
    }

    // tail: n % 4 leftover handled by the first thread of block 0
    if (blockIdx.x == 0 && threadIdx.x == 0) {
        for (int i = nquad * 4; i < n; i++) {
            float m;
            if (MODE == 0)      m = ((const float*)mask)[i];
            else if (MODE == 1) m = ((const uint8_t*)mask)[i] ? 1.0f : 0.0f;
            else                m = ((const int*)mask)[i] ? 1.0f : 0.0f;
            iou_out[i] = ciou_elem(pb[i], tb[i], m, box_norm[i], acc);
        }
    }
    return acc;
}

__global__ void __launch_bounds__(NTHREADS)
ciou_fused_kernel(const float4* __restrict__ pb,
                  const float4* __restrict__ tb,
                  const void*   __restrict__ mask,
                  const float*  __restrict__ box_norm,
                  const float*  __restrict__ cls_norm,
                  float*        __restrict__ out,
                  int n) {
    const int mode = sniff_mask_mode((const uint32_t*)mask);
    float* __restrict__ iou_out = out + 1;

    float acc;
    if (mode == 0)      acc = quad_work<0>(pb, tb, mask, box_norm, iou_out, n);
    else if (mode == 1) acc = quad_work<1>(pb, tb, mask, box_norm, iou_out, n);
    else                acc = quad_work<2>(pb, tb, mask, box_norm, iou_out, n);

    float bsum = block_reduce_sum(acc);

    __shared__ int s_is_last;
    if (threadIdx.x == 0) {
        g_partials[blockIdx.x] = bsum;
        __threadfence();
        unsigned prev = atomicAdd(&g_ticket, 1u);
        s_is_last = (prev == (unsigned)(gridDim.x - 1));
    }
    __syncthreads();

    if (s_is_last) {
        float v = 0.0f;
        int nb = gridDim.x;
        for (int i = threadIdx.x; i < nb; i += NTHREADS)
            v += g_partials[i];
        float total = block_reduce_sum(v);
        if (threadIdx.x == 0) {
            out[0] = total / cls_norm[0];
            g_ticket = 0;
        }
    }
}

extern "C" void kernel_launch(void* const* d_in, const int* in_sizes, int n_in,
                              void* d_out, int out_size) {
    const float4*  pb       = (const float4*)d_in[0];
    const float4*  tb       = (const float4*)d_in[1];
    const void*    mask     = d_in[2];
    const float*   box_norm = (const float*)d_in[3];
    const float*   cls_norm = (const float*)d_in[4];
    float*         out      = (float*)d_out;

    int n = in_sizes[2];
    int nquad = n >> 2;
    int grid  = (nquad + NTHREADS - 1) / NTHREADS;
    if (grid < 1) grid = 1;
    if (grid > MAX_BLOCKS) grid = MAX_BLOCKS;   // n=2.15M -> 2100 blocks, fits

    ciou_fused_kernel<<<grid, NTHREADS>>>(pb, tb, mask, box_norm,
                                          cls_norm, out, n);
}

// round 5
// speedup vs baseline: 1.2424x; 1.2424x over previous
#include <cuda_runtime.h>
#include <stdint.h>
#include <math_constants.h>

// BoxLoss: elementwise CIoU + masked reduction, fused single kernel.
//   0: predicts_bbox [B,A,4] f32
//   1: targets_bbox  [B,A,4] f32
//   2: valid_masks   [B,A]   bool/f32/i32 (dtype sniffed per-block)
//   3: box_norm      [B,A]   f32
//   4: cls_norm      []      f32
// Output: d_out[0] = loss_iou, d_out[1..N] = masked iou.

#define NBLOCKS  1184
#define NTHREADS 256

__device__ float        g_partials[NBLOCKS];
__device__ unsigned int g_ticket = 0;

__device__ __forceinline__ int sniff_mask_mode(const uint32_t* mask_words) {
    uint32_t w = mask_words[threadIdx.x];          // first 1024 bytes
    int f32flag = 0, u8flag = 0;
    #pragma unroll
    for (int b = 0; b < 4; b++) {
        uint32_t byte = (w >> (8 * b)) & 0xFFu;
        if (byte == 0x3Fu || byte == 0x80u) f32flag = 1;
        if (byte == 0x01u && b != 0)        u8flag  = 1;
    }
    unsigned any_f32 = __ballot_sync(0xFFFFFFFFu, f32flag);
    unsigned any_u8  = __ballot_sync(0xFFFFFFFFu, u8flag);

    __shared__ int s_f32, s_u8, s_mode;
    if (threadIdx.x == 0) { s_f32 = 0; s_u8 = 0; }
    __syncthreads();
    if ((threadIdx.x & 31) == 0) {
        if (any_f32) atomicOr(&s_f32, 1);
        if (any_u8)  atomicOr(&s_u8, 1);
    }
    __syncthreads();
    if (threadIdx.x == 0) s_mode = s_f32 ? 0 : (s_u8 ? 1 : 2);
    __syncthreads();
    return s_mode;
}

__device__ __forceinline__ float block_reduce_sum(float v) {
    __shared__ float s_warp[NTHREADS / 32];
    #pragma unroll
    for (int off = 16; off > 0; off >>= 1)
        v += __shfl_down_sync(0xFFFFFFFFu, v, off);
    int lane = threadIdx.x & 31;
    int wid  = threadIdx.x >> 5;
    if (lane == 0) s_warp[wid] = v;
    __syncthreads();
    float r = 0.0f;
    if (threadIdx.x == 0) {
        #pragma unroll
        for (int w = 0; w < NTHREADS / 32; w++) r += s_warp[w];
    }
    return r;  // valid in thread 0 only
}

// branchless minimax atan, full range, max err ~1e-6
__device__ __forceinline__ float fast_atan(float t) {
    float at  = fabsf(t);
    bool  inv = at > 1.0f;
    float z   = inv ? __fdividef(1.0f, at) : at;   // z in [0,1]
    float z2  = z * z;
    float p   =              -0.0117212f;
    p = fmaf(p, z2,  0.05265332f);
    p = fmaf(p, z2, -0.11643287f);
    p = fmaf(p, z2,  0.19354346f);
    p = fmaf(p, z2, -0.33262347f);
    p = fmaf(p, z2,  0.99997726f);
    p *= z;
    float r = inv ? (CUDART_PIO2_F - p) : p;
    return copysignf(r, t);
}

// one element of masked CIoU; returns masked iou, accumulates loss term
__device__ __forceinline__ float ciou_elem(float4 a, float4 b, float m,
                                           float bn, float& acc) {
    const float EPS   = 1e-9f;
    const float C4PI2 = 4.0f / (CUDART_PI_F * CUDART_PI_F);

    float iw = fmaxf(fminf(a.z, b.z) - fmaxf(a.x, b.x), 0.0f);
    float ih = fmaxf(fminf(a.w, b.w) - fmaxf(a.y, b.y), 0.0f);
    float inter  = iw * ih;
    float wa = a.z - a.x, ha = a.w - a.y;
    float wb = b.z - b.x, hb = b.w - b.y;
    float uni = wa * ha + wb * hb - inter;
    float iou = __fdividef(inter, uni + EPS);

    float cw = fmaxf(a.z, b.z) - fminf(a.x, b.x);
    float ch = fmaxf(a.w, b.w) - fminf(a.y, b.y);
    float c2 = cw * cw + ch * ch + EPS;

    float dx   = (b.x + b.z - a.x - a.z) * 0.5f;
    float dy   = (b.y + b.w - a.y - a.w) * 0.5f;
    float rho2 = dx * dx + dy * dy;

    // atan(x) - atan(y) == atan((x-y)/(1+xy))  for x,y >= 0 (no wrap)
    float x = __fdividef(wb, hb + EPS);
    float y = __fdividef(wa, ha + EPS);
    float t = __fdividef(x - y, fmaf(x, y, 1.0f));
    float d = fast_atan(t);
    float v = C4PI2 * d * d;
    float alpha = __fdividef(v, 1.0f - iou + v + EPS);

    float ciou_m = (iou - __fdividef(rho2, c2) - alpha * v) * m;
    acc += (1.0f - ciou_m) * bn * m;
    return ciou_m;
}

template <int MODE>
__device__ __forceinline__ float mainloop(const float4* __restrict__ pb,
                                          const float4* __restrict__ tb,
                                          const void*   __restrict__ mask,
                                          const float*  __restrict__ box_norm,
                                          float*        __restrict__ iou_out,
                                          int n) {
    float acc = 0.0f;
    int tid    = blockIdx.x * blockDim.x + threadIdx.x;
    int stride = gridDim.x * blockDim.x;
    int npair  = n >> 1;

    for (int p = tid; p < npair; p += stride) {
        int i = p * 2;
        // batch all loads up front (MLP)
        float4 a0 = pb[i],     a1 = pb[i + 1];
        float4 b0 = tb[i],     b1 = tb[i + 1];
        float2 bn = ((const float2*)box_norm)[p];
        float  m0, m1;
        if (MODE == 0) {
            float2 mm = ((const float2*)mask)[p];
            m0 = mm.x; m1 = mm.y;
        } else if (MODE == 1) {
            uchar2 mm = ((const uchar2*)mask)[p];
            m0 = mm.x ? 1.0f : 0.0f; m1 = mm.y ? 1.0f : 0.0f;
        } else {
            int2 mm = ((const int2*)mask)[p];
            m0 = mm.x ? 1.0f : 0.0f; m1 = mm.y ? 1.0f : 0.0f;
        }
        iou_out[i]     = ciou_elem(a0, b0, m0, bn.x, acc);
        iou_out[i + 1] = ciou_elem(a1, b1, m1, bn.y, acc);
    }
    // odd tail
    if ((n & 1) && tid == 0) {
        int i = n - 1;
        float m;
        if (MODE == 0)      m = ((const float*)mask)[i];
        else if (MODE == 1) m = ((const uint8_t*)mask)[i] ? 1.0f : 0.0f;
        else                m = ((const int*)mask)[i] ? 1.0f : 0.0f;
        iou_out[i] = ciou_elem(pb[i], tb[i], m, box_norm[i], acc);
    }
    return acc;
}

__global__ void __launch_bounds__(NTHREADS)
ciou_fused_kernel(const float4* __restrict__ pb,
                  const float4* __restrict__ tb,
                  const void*   __restrict__ mask,
                  const float*  __restrict__ box_norm,
                  const float*  __restrict__ cls_norm,
                  float*        __restrict__ out,
                  int n) {
    const int mode = sniff_mask_mode((const uint32_t*)mask);
    float* __restrict__ iou_out = out + 1;

    float acc;
    if (mode == 0)      acc = mainloop<0>(pb, tb, mask, box_norm, iou_out, n);
    else if (mode == 1) acc = mainloop<1>(pb, tb, mask, box_norm, iou_out, n);
    else                acc = mainloop<2>(pb, tb, mask, box_norm, iou_out, n);

    float bsum = block_reduce_sum(acc);

    __shared__ int s_is_last;
    if (threadIdx.x == 0) {
        g_partials[blockIdx.x] = bsum;
        __threadfence();
        unsigned prev = atomicAdd(&g_ticket, 1u);
        s_is_last = (prev == (unsigned)(gridDim.x - 1));
    }
    __syncthreads();

    if (s_is_last) {
        float v = 0.0f;
        for (int i = threadIdx.x; i < NBLOCKS; i += NTHREADS)
            v += g_partials[i];
        float total = block_reduce_sum(v);
        if (threadIdx.x == 0) {
            out[0] = total / cls_norm[0];
            g_ticket = 0;
        }
    }
}

extern "C" void kernel_launch(void* const* d_in, const int* in_sizes, int n_in,
                              void* d_out, int out_size) {
    const float4*  pb       = (const float4*)d_in[0];
    const float4*  tb       = (const float4*)d_in[1];
    const void*    mask     = d_in[2];
    const float*   box_norm = (const float*)d_in[3];
    const float*   cls_norm = (const float*)d_in[4];
    float*         out      = (float*)d_out;

    int n = in_sizes[2];

    ciou_fused_kernel<<<NBLOCKS, NTHREADS>>>(pb, tb, mask, box_norm,
                                             cls_norm, out, n);
}